// round 11
// baseline (speedup 1.0000x reference)
#include <cuda_runtime.h>
#include <cuda_bf16.h>
#include <mma.h>
#include <cstdint>

using namespace nvcuda;

// x: (32, 4096, 1024) f32 ; seeds: (32, 1024) ; proj_w: (1024, 32768) ; proj_b: (1024)
// out: (32, 1024) f32
#define Bb 32
#define Nn 4096
#define Dd 1024
#define Ss 32
#define Pp 1024
#define Ff 32768

__device__ float g_scores[(size_t)Bb * Ss * Nn];   // 16 MB [b][s][n]
__device__ float g_flat[(size_t)Bb * Ff];          // 4 MB  [b][s*1024+d]
__device__ float g_qpart[(size_t)16 * Bb * Pp];    // 2 MB  [ks][b][p]

typedef wmma::fragment<wmma::matrix_a, 16, 16, 16, __nv_bfloat16, wmma::row_major> FragA;
typedef wmma::fragment<wmma::matrix_b, 16, 16, 16, __nv_bfloat16, wmma::col_major> FragBc;
typedef wmma::fragment<wmma::matrix_b, 16, 16, 16, __nv_bfloat16, wmma::row_major> FragBr;
typedef wmma::fragment<wmma::accumulator, 16, 16, 16, float> FragC;

// pads (elements): odd multiples of 8 -> 16B-quad shifts 1 per row -> conflict-free ldsm
#define PAD_A 72     // 64-wide k tiles
#define PAD_X 136    // 128-wide d tiles

__device__ __forceinline__ void sts128s(__nv_bfloat16* p, uint4 v) {
    *(uint4*)p = v;
}

// split 8 f32 -> 8 bf16 hi + 8 bf16 lo
__device__ __forceinline__ void split8(const float4& a, const float4& b, uint4& hi, uint4& lo) {
    float f[8] = {a.x, a.y, a.z, a.w, b.x, b.y, b.z, b.w};
    uint32_t hh[4], ll[4];
#pragma unroll
    for (int i = 0; i < 4; i++) {
        float x0 = f[2 * i], x1 = f[2 * i + 1];
        __nv_bfloat16 h0 = __float2bfloat16(x0), h1 = __float2bfloat16(x1);
        float r0 = x0 - __bfloat162float(h0), r1 = x1 - __bfloat162float(h1);
        __nv_bfloat16 l0 = __float2bfloat16(r0), l1 = __float2bfloat16(r1);
        __nv_bfloat162 hp(h0, h1), lp(l0, l1);
        hh[i] = *(uint32_t*)&hp;
        ll[i] = *(uint32_t*)&lp;
    }
    hi = make_uint4(hh[0], hh[1], hh[2], hh[3]);
    lo = make_uint4(ll[0], ll[1], ll[2], ll[3]);
}

// ---- register tiles (gmem f32) + padded bf16 smem staging ----
struct TA { float4 v[8]; };   // 128 rows x 64 k, thread: row=t>>1, half=t&1
__device__ __forceinline__ void ldA(TA& r, const float* base, int ld, int k0, int t) {
    const float* p = base + (size_t)(t >> 1) * ld + k0 + (t & 1) * 32;
#pragma unroll
    for (int j = 0; j < 8; j++) r.v[j] = __ldg((const float4*)(p + 4 * j));
}
__device__ __forceinline__ void stA_p(const TA& r, __nv_bfloat16* hiB, __nv_bfloat16* loB, int t) {
    int row = t >> 1, half = t & 1;
#pragma unroll
    for (int j = 0; j < 4; j++) {
        uint4 h, l;
        split8(r.v[2 * j], r.v[2 * j + 1], h, l);
        int off = row * PAD_A + half * 32 + j * 8;
        sts128s(hiB + off, h);
        sts128s(loB + off, l);
    }
}
struct TB { float4 v[2]; };   // 32 rows x 64 k, thread: row=t>>3, seg=t&7
__device__ __forceinline__ void ldB(TB& r, const float* base, int ld, int k0, int t) {
    const float* p = base + (size_t)(t >> 3) * ld + k0 + (t & 7) * 8;
    r.v[0] = __ldg((const float4*)p);
    r.v[1] = __ldg((const float4*)(p + 4));
}
__device__ __forceinline__ void stB_p(const TB& r, __nv_bfloat16* hiB, __nv_bfloat16* loB, int t) {
    int row = t >> 3, seg = t & 7;
    uint4 h, l;
    split8(r.v[0], r.v[1], h, l);
    int off = row * PAD_A + seg * 8;
    sts128s(hiB + off, h);
    sts128s(loB + off, l);
}
struct TX { float4 v[8]; };   // 64 n-rows x 128 d, thread: n=t>>2, dseg=t&3
__device__ __forceinline__ void ldX(TX& r, const float* base, int n0, int t) {
    const float* p = base + (size_t)(n0 + (t >> 2)) * Dd + (t & 3) * 32;
#pragma unroll
    for (int j = 0; j < 8; j++) r.v[j] = __ldg((const float4*)(p + 4 * j));
}
__device__ __forceinline__ void stX_p(const TX& r, __nv_bfloat16* hiB, __nv_bfloat16* loB, int t) {
    int nl = t >> 2, dseg = t & 3;
#pragma unroll
    for (int j = 0; j < 4; j++) {
        uint4 h, l;
        split8(r.v[2 * j], r.v[2 * j + 1], h, l);
        int off = nl * PAD_X + dseg * 32 + j * 8;
        sts128s(hiB + off, h);
        sts128s(loB + off, l);
    }
}

// ---------------------------------------------------------------------------
// K1: scores[b][s][n] = (1/32) * x[b] . seeds^T.  C[m=n 128][n'=s 32].
// grid (32 n-tiles, 32 b), 256 thr. 8 warps: warp w -> m strip w*16, 2 s-tiles.
// ---------------------------------------------------------------------------
__global__ void __launch_bounds__(256) k1_scores(const float* __restrict__ x,
                                                 const float* __restrict__ seeds) {
    __shared__ __nv_bfloat16 AH[128 * PAD_A], AL[128 * PAD_A];
    __shared__ __nv_bfloat16 BH[32 * PAD_A], BL[32 * PAD_A];
    int t = threadIdx.x, w = t >> 5;
    int nt = blockIdx.x, b = blockIdx.y;
    const float* A = x + (size_t)b * Nn * Dd + (size_t)nt * 128 * Dd;

    TA ra; TB rb;
    ldA(ra, A, Dd, 0, t);
    ldB(rb, seeds, Dd, 0, t);

    FragC acc[2];
    wmma::fill_fragment(acc[0], 0.0f);
    wmma::fill_fragment(acc[1], 0.0f);

    const int NCH = 16;
    for (int ch = 0; ch < NCH; ch++) {
        __syncthreads();
        stA_p(ra, AH, AL, t);
        stB_p(rb, BH, BL, t);
        __syncthreads();
        if (ch + 1 < NCH) { ldA(ra, A, Dd, (ch + 1) * 64, t); ldB(rb, seeds, Dd, (ch + 1) * 64, t); }
#pragma unroll
        for (int ks = 0; ks < 4; ks++) {
            FragA fah, fal;
            wmma::load_matrix_sync(fah, AH + w * 16 * PAD_A + ks * 16, PAD_A);
            wmma::load_matrix_sync(fal, AL + w * 16 * PAD_A + ks * 16, PAD_A);
#pragma unroll
            for (int j = 0; j < 2; j++) {
                FragBc fbh, fbl;
                wmma::load_matrix_sync(fbh, BH + j * 16 * PAD_A + ks * 16, PAD_A);
                wmma::load_matrix_sync(fbl, BL + j * 16 * PAD_A + ks * 16, PAD_A);
                wmma::mma_sync(acc[j], fah, fbh, acc[j]);
                wmma::mma_sync(acc[j], fal, fbh, acc[j]);
                wmma::mma_sync(acc[j], fah, fbl, acc[j]);
            }
        }
    }
#pragma unroll
    for (int j = 0; j < 2; j++) {
#pragma unroll
        for (int i = 0; i < acc[j].num_elements; i++) acc[j].x[i] *= 0.03125f;
        // C(m,n') -> g_scores[b][n'][nt*128 + m] : col_major, ldm = Nn
        float* ptr = g_scores + (size_t)b * Ss * Nn + (size_t)(j * 16) * Nn + nt * 128 + w * 16;
        wmma::store_matrix_sync(ptr, acc[j], Nn, wmma::mem_col_major);
    }
}

// ---------------------------------------------------------------------------
// softmax over n per (b,s). grid 1024 x 256.
// ---------------------------------------------------------------------------
__global__ void k_softmax() {
    __shared__ float red[256];
    const int t = threadIdx.x;
    float* row = g_scores + (size_t)blockIdx.x * Nn;
    float v[16];
    float m = -1e30f;
#pragma unroll
    for (int i = 0; i < 16; i++) { v[i] = row[t + 256 * i]; m = fmaxf(m, v[i]); }
    red[t] = m;
    __syncthreads();
    for (int o = 128; o > 0; o >>= 1) { if (t < o) red[t] = fmaxf(red[t], red[t + o]); __syncthreads(); }
    m = red[0];
    __syncthreads();
    float sum = 0.f;
#pragma unroll
    for (int i = 0; i < 16; i++) { v[i] = __expf(v[i] - m); sum += v[i]; }
    red[t] = sum;
    __syncthreads();
    for (int o = 128; o > 0; o >>= 1) { if (t < o) red[t] += red[t + o]; __syncthreads(); }
    float inv = 1.0f / red[0];
#pragma unroll
    for (int i = 0; i < 16; i++) row[t + 256 * i] = v[i] * inv;
}

// ---------------------------------------------------------------------------
// K2: pooled[b][s][d] = attn[b] . x[b].  C[m=s 32][n'=d 128-tile].
// grid (8 d-tiles, 32 b). warp (mw=w>>2, nw=w&3): m strip mw*16, n = nw*16 + {0,64}.
// B = x natural [n][d] = row_major matrix_b. No transpose anywhere.
// ---------------------------------------------------------------------------
__global__ void __launch_bounds__(256) k2_pool(const float* __restrict__ x) {
    __shared__ __nv_bfloat16 SH[32 * PAD_A], SL[32 * PAD_A];     // attn tile
    __shared__ __nv_bfloat16 XH[64 * PAD_X], XL[64 * PAD_X];     // x tile
    int t = threadIdx.x, w = t >> 5;
    int mw = w >> 2, nw = w & 3;
    int dt = blockIdx.x, b = blockIdx.y;
    const float* At = g_scores + (size_t)b * Ss * Nn;
    const float* Bx = x + (size_t)b * Nn * Dd + dt * 128;

    TB ra; TX rx;
    ldB(ra, At, Nn, 0, t);
    ldX(rx, Bx, 0, t);

    FragC acc[2];
    wmma::fill_fragment(acc[0], 0.0f);
    wmma::fill_fragment(acc[1], 0.0f);

    const int NCH = 64;
    for (int ch = 0; ch < NCH; ch++) {
        __syncthreads();
        stB_p(ra, SH, SL, t);
        stX_p(rx, XH, XL, t);
        __syncthreads();
        if (ch + 1 < NCH) { ldB(ra, At, Nn, (ch + 1) * 64, t); ldX(rx, Bx, (ch + 1) * 64, t); }
#pragma unroll
        for (int ks = 0; ks < 4; ks++) {
            FragA fah, fal;
            wmma::load_matrix_sync(fah, SH + mw * 16 * PAD_A + ks * 16, PAD_A);
            wmma::load_matrix_sync(fal, SL + mw * 16 * PAD_A + ks * 16, PAD_A);
#pragma unroll
            for (int u = 0; u < 2; u++) {
                int n0 = nw * 16 + u * 64;
                FragBr fbh, fbl;
                wmma::load_matrix_sync(fbh, XH + ks * 16 * PAD_X + n0, PAD_X);
                wmma::load_matrix_sync(fbl, XL + ks * 16 * PAD_X + n0, PAD_X);
                wmma::mma_sync(acc[u], fah, fbh, acc[u]);
                wmma::mma_sync(acc[u], fal, fbh, acc[u]);
                wmma::mma_sync(acc[u], fah, fbl, acc[u]);
            }
        }
    }
#pragma unroll
    for (int u = 0; u < 2; u++) {
        // C(m=s, n=d) -> g_flat[b][s*1024 + dt*128 + n] : row_major, ldm = Dd
        float* ptr = g_flat + (size_t)b * Ff + (size_t)(mw * 16) * Dd + dt * 128 + nw * 16 + u * 64;
        wmma::store_matrix_sync(ptr, acc[u], Dd, wmma::mem_row_major);
    }
}

// ---------------------------------------------------------------------------
// K3: qpart[ks][b'][p] = flat[b'][ks slice] . W[p][ks slice]^T.
// C[m=p 128][n'=b' 32]. grid (16 ks, 8 p-tiles).
// ---------------------------------------------------------------------------
__global__ void __launch_bounds__(256) k3_proj(const float* __restrict__ W) {
    __shared__ __nv_bfloat16 AH[128 * PAD_A], AL[128 * PAD_A];
    __shared__ __nv_bfloat16 BH[32 * PAD_A], BL[32 * PAD_A];
    int t = threadIdx.x, w = t >> 5;
    int ks = blockIdx.x, pt = blockIdx.y;
    const float* A = W + (size_t)pt * 128 * Ff + ks * 2048;
    const float* Bm = g_flat + ks * 2048;

    TA ra; TB rb;
    ldA(ra, A, Ff, 0, t);
    ldB(rb, Bm, Ff, 0, t);

    FragC acc[2];
    wmma::fill_fragment(acc[0], 0.0f);
    wmma::fill_fragment(acc[1], 0.0f);

    const int NCH = 32;
    for (int ch = 0; ch < NCH; ch++) {
        __syncthreads();
        stA_p(ra, AH, AL, t);
        stB_p(rb, BH, BL, t);
        __syncthreads();
        if (ch + 1 < NCH) { ldA(ra, A, Ff, (ch + 1) * 64, t); ldB(rb, Bm, Ff, (ch + 1) * 64, t); }
#pragma unroll
        for (int kk = 0; kk < 4; kk++) {
            FragA fah, fal;
            wmma::load_matrix_sync(fah, AH + w * 16 * PAD_A + kk * 16, PAD_A);
            wmma::load_matrix_sync(fal, AL + w * 16 * PAD_A + kk * 16, PAD_A);
#pragma unroll
            for (int j = 0; j < 2; j++) {
                FragBc fbh, fbl;
                wmma::load_matrix_sync(fbh, BH + j * 16 * PAD_A + kk * 16, PAD_A);
                wmma::load_matrix_sync(fbl, BL + j * 16 * PAD_A + kk * 16, PAD_A);
                wmma::mma_sync(acc[j], fah, fbh, acc[j]);
                wmma::mma_sync(acc[j], fal, fbh, acc[j]);
                wmma::mma_sync(acc[j], fah, fbl, acc[j]);
            }
        }
    }
#pragma unroll
    for (int j = 0; j < 2; j++) {
        // C(m=p, n=b') -> g_qpart[ks][b'][pt*128 + m] : col_major, ldm = Pp
        float* ptr = g_qpart + (size_t)ks * Bb * Pp + (size_t)(j * 16) * Pp + pt * 128 + w * 16;
        wmma::store_matrix_sync(ptr, acc[j], Pp, wmma::mem_col_major);
    }
}

// out[b][p] = bias[p] + sum_{ks<16} qpart. grid 128 x 256.
__global__ void k_out(const float* __restrict__ bias, float* __restrict__ out) {
    int i = blockIdx.x * 256 + threadIdx.x;
    int p = i & 1023;
    float s = bias[p];
#pragma unroll
    for (int ks = 0; ks < 16; ks++) s += g_qpart[(size_t)ks * Bb * Pp + i];
    out[i] = s;
}

// ---------------------------------------------------------------------------
extern "C" void kernel_launch(void* const* d_in, const int* in_sizes, int n_in,
                              void* d_out, int out_size) {
    const float* x = nullptr; const float* seeds = nullptr;
    const float* W = nullptr; const float* bias = nullptr;
    for (int i = 0; i < n_in; i++) {
        switch (in_sizes[i]) {
            case 134217728: x     = (const float*)d_in[i]; break;
            case 33554432:  W     = (const float*)d_in[i]; break;
            case 32768:     seeds = (const float*)d_in[i]; break;
            case 1024:      bias  = (const float*)d_in[i]; break;
        }
    }
    float* out = (float*)d_out;

    k1_scores<<<dim3(32, 32), 256>>>(x, seeds);
    k_softmax<<<Bb * Ss, 256>>>();
    k2_pool<<<dim3(8, 32), 256>>>(x);
    k3_proj<<<dim3(16, 8), 256>>>(W);
    k_out<<<(Bb * Pp) / 256, 256>>>(bias, out);
}

// round 13
// speedup vs baseline: 1.0589x; 1.0589x over previous
#include <cuda_runtime.h>
#include <cuda_bf16.h>
#include <mma.h>
#include <cstdint>

using namespace nvcuda;

// x: (32, 4096, 1024) f32 ; seeds: (32, 1024) ; proj_w: (1024, 32768) ; proj_b: (1024)
// out: (32, 1024) f32
#define Bb 32
#define Nn 4096
#define Dd 1024
#define Ss 32
#define Pp 1024
#define Ff 32768

__device__ float g_scores[(size_t)Bb * Ss * Nn];    // 16 MB [b][s][n]
__device__ float g_ppart[(size_t)4 * Bb * Ff];      // 16 MB [ks][b][s][d]
__device__ float g_flat[(size_t)Bb * Ff];           // 4 MB  [b][s*1024+d]
__device__ float g_qpart[(size_t)32 * Bb * Pp];     // 4 MB  [ks][b][p]

typedef wmma::fragment<wmma::matrix_a, 16, 16, 16, __nv_bfloat16, wmma::row_major> FragA;
typedef wmma::fragment<wmma::matrix_b, 16, 16, 16, __nv_bfloat16, wmma::col_major> FragBc;
typedef wmma::fragment<wmma::matrix_b, 16, 16, 16, __nv_bfloat16, wmma::row_major> FragBr;
typedef wmma::fragment<wmma::accumulator, 16, 16, 16, float> FragC;

// pads (elements): odd multiples of 8 -> 16B-quad shifts 1 per row -> conflict-free ldsm
#define PAD_A 72     // 64-wide k tiles
#define PAD_X 136    // 128-wide d tiles

// element counts
#define A_ELEMS (128 * PAD_A)   // 9216
#define B_ELEMS (32 * PAD_A)    // 2304
#define X_ELEMS (64 * PAD_X)    // 8704
#define BUF1 (2 * A_ELEMS + 2 * B_ELEMS)   // 23040 elems = 46080 B  (K1/K3)
#define BUF2 (2 * B_ELEMS + 2 * X_ELEMS)   // 22016 elems = 44032 B  (K2)

__device__ __forceinline__ void sts128s(__nv_bfloat16* p, uint4 v) {
    *(uint4*)p = v;
}

// split 8 f32 -> 8 bf16 hi + 8 bf16 lo
__device__ __forceinline__ void split8(const float4& a, const float4& b, uint4& hi, uint4& lo) {
    float f[8] = {a.x, a.y, a.z, a.w, b.x, b.y, b.z, b.w};
    uint32_t hh[4], ll[4];
#pragma unroll
    for (int i = 0; i < 4; i++) {
        float x0 = f[2 * i], x1 = f[2 * i + 1];
        __nv_bfloat16 h0 = __float2bfloat16(x0), h1 = __float2bfloat16(x1);
        float r0 = x0 - __bfloat162float(h0), r1 = x1 - __bfloat162float(h1);
        __nv_bfloat16 l0 = __float2bfloat16(r0), l1 = __float2bfloat16(r1);
        __nv_bfloat162 hp(h0, h1), lp(l0, l1);
        hh[i] = *(uint32_t*)&hp;
        ll[i] = *(uint32_t*)&lp;
    }
    hi = make_uint4(hh[0], hh[1], hh[2], hh[3]);
    lo = make_uint4(ll[0], ll[1], ll[2], ll[3]);
}

// ---- register tiles (gmem f32) + padded bf16 smem staging ----
struct TA { float4 v[8]; };   // 128 rows x 64 k, thread: row=t>>1, half=t&1
__device__ __forceinline__ void ldA(TA& r, const float* base, int ld, int k0, int t) {
    const float* p = base + (size_t)(t >> 1) * ld + k0 + (t & 1) * 32;
#pragma unroll
    for (int j = 0; j < 8; j++) r.v[j] = __ldg((const float4*)(p + 4 * j));
}
__device__ __forceinline__ void stA_p(const TA& r, __nv_bfloat16* hiB, __nv_bfloat16* loB, int t) {
    int row = t >> 1, half = t & 1;
#pragma unroll
    for (int j = 0; j < 4; j++) {
        uint4 h, l;
        split8(r.v[2 * j], r.v[2 * j + 1], h, l);
        int off = row * PAD_A + half * 32 + j * 8;
        sts128s(hiB + off, h);
        sts128s(loB + off, l);
    }
}
struct TB { float4 v[2]; };   // 32 rows x 64 k, thread: row=t>>3, seg=t&7
__device__ __forceinline__ void ldB(TB& r, const float* base, int ld, int k0, int t) {
    const float* p = base + (size_t)(t >> 3) * ld + k0 + (t & 7) * 8;
    r.v[0] = __ldg((const float4*)p);
    r.v[1] = __ldg((const float4*)(p + 4));
}
__device__ __forceinline__ void stB_p(const TB& r, __nv_bfloat16* hiB, __nv_bfloat16* loB, int t) {
    int row = t >> 3, seg = t & 7;
    uint4 h, l;
    split8(r.v[0], r.v[1], h, l);
    int off = row * PAD_A + seg * 8;
    sts128s(hiB + off, h);
    sts128s(loB + off, l);
}
struct TX { float4 v[8]; };   // 64 n-rows x 128 d, thread: n=t>>2, dseg=t&3
__device__ __forceinline__ void ldX(TX& r, const float* base, int n0, int t) {
    const float* p = base + (size_t)(n0 + (t >> 2)) * Dd + (t & 3) * 32;
#pragma unroll
    for (int j = 0; j < 8; j++) r.v[j] = __ldg((const float4*)(p + 4 * j));
}
__device__ __forceinline__ void stX_p(const TX& r, __nv_bfloat16* hiB, __nv_bfloat16* loB, int t) {
    int nl = t >> 2, dseg = t & 3;
#pragma unroll
    for (int j = 0; j < 4; j++) {
        uint4 h, l;
        split8(r.v[2 * j], r.v[2 * j + 1], h, l);
        int off = nl * PAD_X + dseg * 32 + j * 8;
        sts128s(hiB + off, h);
        sts128s(loB + off, l);
    }
}

// shared GEMM body for the "A 128 x B 32 (col-major)" shape (K1 & K3)
// per chunk: store -> ONE sync -> prefetch + compute from current buffer.
template <int NCH>
__device__ __forceinline__ void gemm128x32(
    const float* A, int lda, const float* B, int ldb,
    FragC acc[2], __nv_bfloat16* dsm, int t, int w)
{
    TA ra; TB rb;
    ldA(ra, A, lda, 0, t);
    ldB(rb, B, ldb, 0, t);
    for (int ch = 0; ch < NCH; ch++) {
        __nv_bfloat16* bf = dsm + (ch & 1) * BUF1;
        __nv_bfloat16* AH = bf;
        __nv_bfloat16* AL = bf + A_ELEMS;
        __nv_bfloat16* BH = bf + 2 * A_ELEMS;
        __nv_bfloat16* BL = bf + 2 * A_ELEMS + B_ELEMS;
        stA_p(ra, AH, AL, t);
        stB_p(rb, BH, BL, t);
        __syncthreads();
        if (ch + 1 < NCH) { ldA(ra, A, lda, (ch + 1) * 64, t); ldB(rb, B, ldb, (ch + 1) * 64, t); }
#pragma unroll
        for (int ks = 0; ks < 4; ks++) {
            FragA fah, fal;
            wmma::load_matrix_sync(fah, AH + w * 16 * PAD_A + ks * 16, PAD_A);
            wmma::load_matrix_sync(fal, AL + w * 16 * PAD_A + ks * 16, PAD_A);
#pragma unroll
            for (int j = 0; j < 2; j++) {
                FragBc fbh, fbl;
                wmma::load_matrix_sync(fbh, BH + j * 16 * PAD_A + ks * 16, PAD_A);
                wmma::load_matrix_sync(fbl, BL + j * 16 * PAD_A + ks * 16, PAD_A);
                wmma::mma_sync(acc[j], fah, fbh, acc[j]);
                wmma::mma_sync(acc[j], fal, fbh, acc[j]);
                wmma::mma_sync(acc[j], fah, fbl, acc[j]);
            }
        }
    }
}

// ---------------------------------------------------------------------------
// K1: scores[b][s][n] = (1/32) * x[b] . seeds^T.  C[m=n 128][n'=s 32].
// grid (32 n-tiles, 32 b), 256 thr. dyn smem 2*BUF1.
// ---------------------------------------------------------------------------
__global__ void __launch_bounds__(256) k1_scores(const float* __restrict__ x,
                                                 const float* __restrict__ seeds) {
    extern __shared__ __nv_bfloat16 dsm[];
    int t = threadIdx.x, w = t >> 5;
    int nt = blockIdx.x, b = blockIdx.y;
    const float* A = x + (size_t)b * Nn * Dd + (size_t)nt * 128 * Dd;

    FragC acc[2];
    wmma::fill_fragment(acc[0], 0.0f);
    wmma::fill_fragment(acc[1], 0.0f);

    gemm128x32<16>(A, Dd, seeds, Dd, acc, dsm, t, w);

#pragma unroll
    for (int j = 0; j < 2; j++) {
#pragma unroll
        for (int i = 0; i < acc[j].num_elements; i++) acc[j].x[i] *= 0.03125f;
        float* ptr = g_scores + (size_t)b * Ss * Nn + (size_t)(j * 16) * Nn + nt * 128 + w * 16;
        wmma::store_matrix_sync(ptr, acc[j], Nn, wmma::mem_col_major);
    }
}

// ---------------------------------------------------------------------------
// softmax over n per (b,s). grid 1024 x 256.
// ---------------------------------------------------------------------------
__global__ void k_softmax() {
    __shared__ float red[256];
    const int t = threadIdx.x;
    float* row = g_scores + (size_t)blockIdx.x * Nn;
    float v[16];
    float m = -1e30f;
#pragma unroll
    for (int i = 0; i < 16; i++) { v[i] = row[t + 256 * i]; m = fmaxf(m, v[i]); }
    red[t] = m;
    __syncthreads();
    for (int o = 128; o > 0; o >>= 1) { if (t < o) red[t] = fmaxf(red[t], red[t + o]); __syncthreads(); }
    m = red[0];
    __syncthreads();
    float sum = 0.f;
#pragma unroll
    for (int i = 0; i < 16; i++) { v[i] = __expf(v[i] - m); sum += v[i]; }
    red[t] = sum;
    __syncthreads();
    for (int o = 128; o > 0; o >>= 1) { if (t < o) red[t] += red[t + o]; __syncthreads(); }
    float inv = 1.0f / red[0];
#pragma unroll
    for (int i = 0; i < 16; i++) row[t + 256 * i] = v[i] * inv;
}

// ---------------------------------------------------------------------------
// K2: pooled partials over 4 n-slices. C[m=s 32][n'=d 128-tile].
// grid (8 dt, 4 ks, 32 b), 256 thr. dyn smem 2*BUF2. NCH=16 (n slice 1024).
// ---------------------------------------------------------------------------
__global__ void __launch_bounds__(256) k2_pool(const float* __restrict__ x) {
    extern __shared__ __nv_bfloat16 dsm[];
    int t = threadIdx.x, w = t >> 5;
    int mw = w >> 2, nw = w & 3;
    int dt = blockIdx.x, ksl = blockIdx.y, b = blockIdx.z;
    const float* At = g_scores + (size_t)b * Ss * Nn + ksl * 1024;
    const float* Bx = x + (size_t)b * Nn * Dd + (size_t)(ksl * 1024) * Dd + dt * 128;

    TB ra; TX rx;
    ldB(ra, At, Nn, 0, t);
    ldX(rx, Bx, 0, t);

    FragC acc[2];
    wmma::fill_fragment(acc[0], 0.0f);
    wmma::fill_fragment(acc[1], 0.0f);

    const int NCH = 16;
    for (int ch = 0; ch < NCH; ch++) {
        __nv_bfloat16* bf = dsm + (ch & 1) * BUF2;
        __nv_bfloat16* SH = bf;
        __nv_bfloat16* SL = bf + B_ELEMS;
        __nv_bfloat16* XH = bf + 2 * B_ELEMS;
        __nv_bfloat16* XL = bf + 2 * B_ELEMS + X_ELEMS;
        stB_p(ra, SH, SL, t);
        stX_p(rx, XH, XL, t);
        __syncthreads();
        if (ch + 1 < NCH) { ldB(ra, At, Nn, (ch + 1) * 64, t); ldX(rx, Bx, (ch + 1) * 64, t); }
#pragma unroll
        for (int ks = 0; ks < 4; ks++) {
            FragA fah, fal;
            wmma::load_matrix_sync(fah, SH + mw * 16 * PAD_A + ks * 16, PAD_A);
            wmma::load_matrix_sync(fal, SL + mw * 16 * PAD_A + ks * 16, PAD_A);
#pragma unroll
            for (int u = 0; u < 2; u++) {
                int n0 = nw * 16 + u * 64;
                FragBr fbh, fbl;
                wmma::load_matrix_sync(fbh, XH + ks * 16 * PAD_X + n0, PAD_X);
                wmma::load_matrix_sync(fbl, XL + ks * 16 * PAD_X + n0, PAD_X);
                wmma::mma_sync(acc[u], fah, fbh, acc[u]);
                wmma::mma_sync(acc[u], fal, fbh, acc[u]);
                wmma::mma_sync(acc[u], fah, fbl, acc[u]);
            }
        }
    }
#pragma unroll
    for (int u = 0; u < 2; u++) {
        float* ptr = g_ppart + (size_t)ksl * Bb * Ff + (size_t)b * Ff
                   + (size_t)(mw * 16) * Dd + dt * 128 + nw * 16 + u * 64;
        wmma::store_matrix_sync(ptr, acc[u], Dd, wmma::mem_row_major);
    }
}

// flat = sum of 4 n-slice partials. grid 4096 x 256.
__global__ void k_flat() {
    size_t i = (size_t)blockIdx.x * 256 + threadIdx.x;
    float s = g_ppart[i] + g_ppart[(size_t)1 * Bb * Ff + i]
            + g_ppart[(size_t)2 * Bb * Ff + i] + g_ppart[(size_t)3 * Bb * Ff + i];
    g_flat[i] = s;
}

// ---------------------------------------------------------------------------
// K3: qpart[ks][b'][p] = flat[b'][ks slice] . W[p][ks slice]^T.
// C[m=p 128][n'=b' 32]. grid (32 ks, 8 pt), NCH=16 (f slice 1024). dyn smem 2*BUF1.
// ---------------------------------------------------------------------------
__global__ void __launch_bounds__(256) k3_proj(const float* __restrict__ W) {
    extern __shared__ __nv_bfloat16 dsm[];
    int t = threadIdx.x, w = t >> 5;
    int ks = blockIdx.x, pt = blockIdx.y;
    const float* A = W + (size_t)pt * 128 * Ff + ks * 1024;
    const float* Bm = g_flat + ks * 1024;

    FragC acc[2];
    wmma::fill_fragment(acc[0], 0.0f);
    wmma::fill_fragment(acc[1], 0.0f);

    gemm128x32<16>(A, Ff, Bm, Ff, acc, dsm, t, w);

#pragma unroll
    for (int j = 0; j < 2; j++) {
        float* ptr = g_qpart + (size_t)ks * Bb * Pp + (size_t)(j * 16) * Pp + pt * 128 + w * 16;
        wmma::store_matrix_sync(ptr, acc[j], Pp, wmma::mem_col_major);
    }
}

// out[b][p] = bias[p] + sum_{ks<32} qpart. grid 128 x 256.
__global__ void k_out(const float* __restrict__ bias, float* __restrict__ out) {
    int i = blockIdx.x * 256 + threadIdx.x;
    int p = i & 1023;
    float s = bias[p];
#pragma unroll 8
    for (int ks = 0; ks < 32; ks++) s += g_qpart[(size_t)ks * Bb * Pp + i];
    out[i] = s;
}

// ---------------------------------------------------------------------------
extern "C" void kernel_launch(void* const* d_in, const int* in_sizes, int n_in,
                              void* d_out, int out_size) {
    const float* x = nullptr; const float* seeds = nullptr;
    const float* W = nullptr; const float* bias = nullptr;
    for (int i = 0; i < n_in; i++) {
        switch (in_sizes[i]) {
            case 134217728: x     = (const float*)d_in[i]; break;
            case 33554432:  W     = (const float*)d_in[i]; break;
            case 32768:     seeds = (const float*)d_in[i]; break;
            case 1024:      bias  = (const float*)d_in[i]; break;
        }
    }
    float* out = (float*)d_out;

    const int smem1 = 2 * BUF1 * (int)sizeof(__nv_bfloat16);   // 92160 B (K1/K3)
    const int smem2 = 2 * BUF2 * (int)sizeof(__nv_bfloat16);   // 88064 B (K2)
    cudaFuncSetAttribute(k1_scores, cudaFuncAttributeMaxDynamicSharedMemorySize, smem1);
    cudaFuncSetAttribute(k2_pool,   cudaFuncAttributeMaxDynamicSharedMemorySize, smem2);
    cudaFuncSetAttribute(k3_proj,   cudaFuncAttributeMaxDynamicSharedMemorySize, smem1);

    k1_scores<<<dim3(32, 32), 256, smem1>>>(x, seeds);
    k_softmax<<<Bb * Ss, 256>>>();
    k2_pool<<<dim3(8, 4, 32), 256, smem2>>>(x);
    k_flat<<<(Bb * Ff) / 256, 256>>>();
    k3_proj<<<dim3(32, 8), 256, smem1>>>(W);
    k_out<<<(Bb * Pp) / 256, 256>>>(bias, out);
}

// round 14
// speedup vs baseline: 1.0720x; 1.0123x over previous
#include <cuda_runtime.h>
#include <cuda_bf16.h>
#include <mma.h>
#include <cstdint>

using namespace nvcuda;

// x: (32, 4096, 1024) f32 ; seeds: (32, 1024) ; proj_w: (1024, 32768) ; proj_b: (1024)
// out: (32, 1024) f32
#define Bb 32
#define Nn 4096
#define Dd 1024
#define Ss 32
#define Pp 1024
#define Ff 32768

__device__ float g_scores[(size_t)Bb * Ss * Nn];    // 16 MB [b][s][n]
__device__ float g_ppart[(size_t)4 * Bb * Ff];      // 16 MB [ks][b][s][d]
__device__ float g_flat[(size_t)Bb * Ff];           // 4 MB  [b][s*1024+d]
__device__ float g_qpart[(size_t)32 * Bb * Pp];     // 4 MB  [ks][b][p]

typedef wmma::fragment<wmma::matrix_a, 16, 16, 16, __nv_bfloat16, wmma::row_major> FragA;
typedef wmma::fragment<wmma::matrix_b, 16, 16, 16, __nv_bfloat16, wmma::col_major> FragBc;
typedef wmma::fragment<wmma::matrix_b, 16, 16, 16, __nv_bfloat16, wmma::row_major> FragBr;
typedef wmma::fragment<wmma::accumulator, 16, 16, 16, float> FragC;

// pads (elements): odd multiples of 8 -> 16B-quad shifts 1 per row -> conflict-free ldsm
#define PAD_A 72     // 64-wide k tiles
#define PAD_X 136    // 128-wide d tiles

// element counts
#define A_ELEMS (128 * PAD_A)   // 9216
#define B_ELEMS (32 * PAD_A)    // 2304
#define X_ELEMS (64 * PAD_X)    // 8704
#define BUF1 (2 * A_ELEMS + 2 * B_ELEMS)   // 23040 elems = 46080 B  (K1/K3)
#define BUF2 (2 * B_ELEMS + 2 * X_ELEMS)   // 22016 elems = 44032 B  (K2)

__device__ __forceinline__ void sts128s(__nv_bfloat16* p, uint4 v) {
    *(uint4*)p = v;
}

// split 8 f32 -> 8 bf16 hi + 8 bf16 lo
__device__ __forceinline__ void split8(const float4& a, const float4& b, uint4& hi, uint4& lo) {
    float f[8] = {a.x, a.y, a.z, a.w, b.x, b.y, b.z, b.w};
    uint32_t hh[4], ll[4];
#pragma unroll
    for (int i = 0; i < 4; i++) {
        float x0 = f[2 * i], x1 = f[2 * i + 1];
        __nv_bfloat16 h0 = __float2bfloat16(x0), h1 = __float2bfloat16(x1);
        float r0 = x0 - __bfloat162float(h0), r1 = x1 - __bfloat162float(h1);
        __nv_bfloat16 l0 = __float2bfloat16(r0), l1 = __float2bfloat16(r1);
        __nv_bfloat162 hp(h0, h1), lp(l0, l1);
        hh[i] = *(uint32_t*)&hp;
        ll[i] = *(uint32_t*)&lp;
    }
    hi = make_uint4(hh[0], hh[1], hh[2], hh[3]);
    lo = make_uint4(ll[0], ll[1], ll[2], ll[3]);
}

// ---- register tiles (gmem f32) + padded bf16 smem staging ----
struct TA { float4 v[8]; };   // 128 rows x 64 k, thread: row=t>>1, half=t&1
__device__ __forceinline__ void ldA(TA& r, const float* base, int ld, int k0, int t) {
    const float* p = base + (size_t)(t >> 1) * ld + k0 + (t & 1) * 32;
#pragma unroll
    for (int j = 0; j < 8; j++) r.v[j] = __ldg((const float4*)(p + 4 * j));
}
__device__ __forceinline__ void stA_p(const TA& r, __nv_bfloat16* hiB, __nv_bfloat16* loB, int t) {
    int row = t >> 1, half = t & 1;
#pragma unroll
    for (int j = 0; j < 4; j++) {
        uint4 h, l;
        split8(r.v[2 * j], r.v[2 * j + 1], h, l);
        int off = row * PAD_A + half * 32 + j * 8;
        sts128s(hiB + off, h);
        sts128s(loB + off, l);
    }
}
struct TB { float4 v[2]; };   // 32 rows x 64 k, thread: row=t>>3, seg=t&7
__device__ __forceinline__ void ldB(TB& r, const float* base, int ld, int k0, int t) {
    const float* p = base + (size_t)(t >> 3) * ld + k0 + (t & 7) * 8;
    r.v[0] = __ldg((const float4*)p);
    r.v[1] = __ldg((const float4*)(p + 4));
}
__device__ __forceinline__ void stB_p(const TB& r, __nv_bfloat16* hiB, __nv_bfloat16* loB, int t) {
    int row = t >> 3, seg = t & 7;
    uint4 h, l;
    split8(r.v[0], r.v[1], h, l);
    int off = row * PAD_A + seg * 8;
    sts128s(hiB + off, h);
    sts128s(loB + off, l);
}
struct TX { float4 v[8]; };   // 64 n-rows x 128 d, thread: n=t>>2, dseg=t&3
__device__ __forceinline__ void ldX(TX& r, const float* base, int n0, int t) {
    const float* p = base + (size_t)(n0 + (t >> 2)) * Dd + (t & 3) * 32;
#pragma unroll
    for (int j = 0; j < 8; j++) r.v[j] = __ldg((const float4*)(p + 4 * j));
}
__device__ __forceinline__ void stX_p(const TX& r, __nv_bfloat16* hiB, __nv_bfloat16* loB, int t) {
    int nl = t >> 2, dseg = t & 3;
#pragma unroll
    for (int j = 0; j < 4; j++) {
        uint4 h, l;
        split8(r.v[2 * j], r.v[2 * j + 1], h, l);
        int off = nl * PAD_X + dseg * 32 + j * 8;
        sts128s(hiB + off, h);
        sts128s(loB + off, l);
    }
}

// shared GEMM body for the "A 128 x B 32 (col-major)" shape (K1 & K3).
// acc[j][par]: accumulators split by k-step parity -> 4 independent MMA chains.
template <int NCH>
__device__ __forceinline__ void gemm128x32(
    const float* A, int lda, const float* B, int ldb,
    FragC acc[2][2], __nv_bfloat16* dsm, int t, int w)
{
    TA ra; TB rb;
    ldA(ra, A, lda, 0, t);
    ldB(rb, B, ldb, 0, t);
    for (int ch = 0; ch < NCH; ch++) {
        __nv_bfloat16* bf = dsm + (ch & 1) * BUF1;
        __nv_bfloat16* AH = bf;
        __nv_bfloat16* AL = bf + A_ELEMS;
        __nv_bfloat16* BH = bf + 2 * A_ELEMS;
        __nv_bfloat16* BL = bf + 2 * A_ELEMS + B_ELEMS;
        stA_p(ra, AH, AL, t);
        stB_p(rb, BH, BL, t);
        __syncthreads();
        if (ch + 1 < NCH) { ldA(ra, A, lda, (ch + 1) * 64, t); ldB(rb, B, ldb, (ch + 1) * 64, t); }
#pragma unroll
        for (int ks = 0; ks < 4; ks++) {
            int par = ks & 1;
            FragA fah, fal;
            wmma::load_matrix_sync(fah, AH + w * 16 * PAD_A + ks * 16, PAD_A);
            wmma::load_matrix_sync(fal, AL + w * 16 * PAD_A + ks * 16, PAD_A);
#pragma unroll
            for (int j = 0; j < 2; j++) {
                FragBc fbh, fbl;
                wmma::load_matrix_sync(fbh, BH + j * 16 * PAD_A + ks * 16, PAD_A);
                wmma::load_matrix_sync(fbl, BL + j * 16 * PAD_A + ks * 16, PAD_A);
                wmma::mma_sync(acc[j][par], fah, fbh, acc[j][par]);
                wmma::mma_sync(acc[j][par], fal, fbh, acc[j][par]);
                wmma::mma_sync(acc[j][par], fah, fbl, acc[j][par]);
            }
        }
    }
}

// ---------------------------------------------------------------------------
// K1: scores[b][s][n] = (1/32) * x[b] . seeds^T.  C[m=n 128][n'=s 32].
// grid (32 n-tiles, 32 b), 256 thr, 2 CTAs/SM. dyn smem 2*BUF1.
// ---------------------------------------------------------------------------
__global__ void __launch_bounds__(256, 2) k1_scores(const float* __restrict__ x,
                                                    const float* __restrict__ seeds) {
    extern __shared__ __nv_bfloat16 dsm[];
    int t = threadIdx.x, w = t >> 5;
    int nt = blockIdx.x, b = blockIdx.y;
    const float* A = x + (size_t)b * Nn * Dd + (size_t)nt * 128 * Dd;

    FragC acc[2][2];
#pragma unroll
    for (int j = 0; j < 2; j++) { wmma::fill_fragment(acc[j][0], 0.0f); wmma::fill_fragment(acc[j][1], 0.0f); }

    gemm128x32<16>(A, Dd, seeds, Dd, acc, dsm, t, w);

#pragma unroll
    for (int j = 0; j < 2; j++) {
#pragma unroll
        for (int i = 0; i < acc[j][0].num_elements; i++)
            acc[j][0].x[i] = (acc[j][0].x[i] + acc[j][1].x[i]) * 0.03125f;
        float* ptr = g_scores + (size_t)b * Ss * Nn + (size_t)(j * 16) * Nn + nt * 128 + w * 16;
        wmma::store_matrix_sync(ptr, acc[j][0], Nn, wmma::mem_col_major);
    }
}

// ---------------------------------------------------------------------------
// softmax over n per (b,s). grid 1024 x 256.
// ---------------------------------------------------------------------------
__global__ void k_softmax() {
    __shared__ float red[256];
    const int t = threadIdx.x;
    float* row = g_scores + (size_t)blockIdx.x * Nn;
    float v[16];
    float m = -1e30f;
#pragma unroll
    for (int i = 0; i < 16; i++) { v[i] = row[t + 256 * i]; m = fmaxf(m, v[i]); }
    red[t] = m;
    __syncthreads();
    for (int o = 128; o > 0; o >>= 1) { if (t < o) red[t] = fmaxf(red[t], red[t + o]); __syncthreads(); }
    m = red[0];
    __syncthreads();
    float sum = 0.f;
#pragma unroll
    for (int i = 0; i < 16; i++) { v[i] = __expf(v[i] - m); sum += v[i]; }
    red[t] = sum;
    __syncthreads();
    for (int o = 128; o > 0; o >>= 1) { if (t < o) red[t] += red[t + o]; __syncthreads(); }
    float inv = 1.0f / red[0];
#pragma unroll
    for (int i = 0; i < 16; i++) row[t + 256 * i] = v[i] * inv;
}

// ---------------------------------------------------------------------------
// K2: pooled partials over 4 n-slices. C[m=s 32][n'=d 128-tile].
// grid (8 dt, 4 ks, 32 b), 256 thr, 2 CTAs/SM. dyn smem 2*BUF2. NCH=16.
// ---------------------------------------------------------------------------
__global__ void __launch_bounds__(256, 2) k2_pool(const float* __restrict__ x) {
    extern __shared__ __nv_bfloat16 dsm[];
    int t = threadIdx.x, w = t >> 5;
    int mw = w >> 2, nw = w & 3;
    int dt = blockIdx.x, ksl = blockIdx.y, b = blockIdx.z;
    const float* At = g_scores + (size_t)b * Ss * Nn + ksl * 1024;
    const float* Bx = x + (size_t)b * Nn * Dd + (size_t)(ksl * 1024) * Dd + dt * 128;

    TB ra; TX rx;
    ldB(ra, At, Nn, 0, t);
    ldX(rx, Bx, 0, t);

    FragC acc[2][2];
#pragma unroll
    for (int u = 0; u < 2; u++) { wmma::fill_fragment(acc[u][0], 0.0f); wmma::fill_fragment(acc[u][1], 0.0f); }

    const int NCH = 16;
    for (int ch = 0; ch < NCH; ch++) {
        __nv_bfloat16* bf = dsm + (ch & 1) * BUF2;
        __nv_bfloat16* SH = bf;
        __nv_bfloat16* SL = bf + B_ELEMS;
        __nv_bfloat16* XH = bf + 2 * B_ELEMS;
        __nv_bfloat16* XL = bf + 2 * B_ELEMS + X_ELEMS;
        stB_p(ra, SH, SL, t);
        stX_p(rx, XH, XL, t);
        __syncthreads();
        if (ch + 1 < NCH) { ldB(ra, At, Nn, (ch + 1) * 64, t); ldX(rx, Bx, (ch + 1) * 64, t); }
#pragma unroll
        for (int ks = 0; ks < 4; ks++) {
            int par = ks & 1;
            FragA fah, fal;
            wmma::load_matrix_sync(fah, SH + mw * 16 * PAD_A + ks * 16, PAD_A);
            wmma::load_matrix_sync(fal, SL + mw * 16 * PAD_A + ks * 16, PAD_A);
#pragma unroll
            for (int u = 0; u < 2; u++) {
                int n0 = nw * 16 + u * 64;
                FragBr fbh, fbl;
                wmma::load_matrix_sync(fbh, XH + ks * 16 * PAD_X + n0, PAD_X);
                wmma::load_matrix_sync(fbl, XL + ks * 16 * PAD_X + n0, PAD_X);
                wmma::mma_sync(acc[u][par], fah, fbh, acc[u][par]);
                wmma::mma_sync(acc[u][par], fal, fbh, acc[u][par]);
                wmma::mma_sync(acc[u][par], fah, fbl, acc[u][par]);
            }
        }
    }
#pragma unroll
    for (int u = 0; u < 2; u++) {
#pragma unroll
        for (int i = 0; i < acc[u][0].num_elements; i++)
            acc[u][0].x[i] += acc[u][1].x[i];
        float* ptr = g_ppart + (size_t)ksl * Bb * Ff + (size_t)b * Ff
                   + (size_t)(mw * 16) * Dd + dt * 128 + nw * 16 + u * 64;
        wmma::store_matrix_sync(ptr, acc[u][0], Dd, wmma::mem_row_major);
    }
}

// flat = sum of 4 n-slice partials. grid 4096 x 256.
__global__ void k_flat() {
    size_t i = (size_t)blockIdx.x * 256 + threadIdx.x;
    float s = g_ppart[i] + g_ppart[(size_t)1 * Bb * Ff + i]
            + g_ppart[(size_t)2 * Bb * Ff + i] + g_ppart[(size_t)3 * Bb * Ff + i];
    g_flat[i] = s;
}

// ---------------------------------------------------------------------------
// K3: qpart[ks][b'][p] = flat[b'][ks slice] . W[p][ks slice]^T.
// C[m=p 128][n'=b' 32]. grid (32 ks, 8 pt), NCH=16. dyn smem 2*BUF1. 2 CTAs/SM.
// ---------------------------------------------------------------------------
__global__ void __launch_bounds__(256, 2) k3_proj(const float* __restrict__ W) {
    extern __shared__ __nv_bfloat16 dsm[];
    int t = threadIdx.x, w = t >> 5;
    int ks = blockIdx.x, pt = blockIdx.y;
    const float* A = W + (size_t)pt * 128 * Ff + ks * 1024;
    const float* Bm = g_flat + ks * 1024;

    FragC acc[2][2];
#pragma unroll
    for (int j = 0; j < 2; j++) { wmma::fill_fragment(acc[j][0], 0.0f); wmma::fill_fragment(acc[j][1], 0.0f); }

    gemm128x32<16>(A, Ff, Bm, Ff, acc, dsm, t, w);

#pragma unroll
    for (int j = 0; j < 2; j++) {
#pragma unroll
        for (int i = 0; i < acc[j][0].num_elements; i++)
            acc[j][0].x[i] += acc[j][1].x[i];
        float* ptr = g_qpart + (size_t)ks * Bb * Pp + (size_t)(j * 16) * Pp + pt * 128 + w * 16;
        wmma::store_matrix_sync(ptr, acc[j][0], Pp, wmma::mem_col_major);
    }
}

// out[b][p] = bias[p] + sum_{ks<32} qpart. grid 128 x 256.
__global__ void k_out(const float* __restrict__ bias, float* __restrict__ out) {
    int i = blockIdx.x * 256 + threadIdx.x;
    int p = i & 1023;
    float s = bias[p];
#pragma unroll 8
    for (int ks = 0; ks < 32; ks++) s += g_qpart[(size_t)ks * Bb * Pp + i];
    out[i] = s;
}

// ---------------------------------------------------------------------------
extern "C" void kernel_launch(void* const* d_in, const int* in_sizes, int n_in,
                              void* d_out, int out_size) {
    const float* x = nullptr; const float* seeds = nullptr;
    const float* W = nullptr; const float* bias = nullptr;
    for (int i = 0; i < n_in; i++) {
        switch (in_sizes[i]) {
            case 134217728: x     = (const float*)d_in[i]; break;
            case 33554432:  W     = (const float*)d_in[i]; break;
            case 32768:     seeds = (const float*)d_in[i]; break;
            case 1024:      bias  = (const float*)d_in[i]; break;
        }
    }
    float* out = (float*)d_out;

    const int smem1 = 2 * BUF1 * (int)sizeof(__nv_bfloat16);   // 92160 B (K1/K3)
    const int smem2 = 2 * BUF2 * (int)sizeof(__nv_bfloat16);   // 88064 B (K2)
    cudaFuncSetAttribute(k1_scores, cudaFuncAttributeMaxDynamicSharedMemorySize, smem1);
    cudaFuncSetAttribute(k2_pool,   cudaFuncAttributeMaxDynamicSharedMemorySize, smem2);
    cudaFuncSetAttribute(k3_proj,   cudaFuncAttributeMaxDynamicSharedMemorySize, smem1);

    k1_scores<<<dim3(32, 32), 256, smem1>>>(x, seeds);
    k_softmax<<<Bb * Ss, 256>>>();
    k2_pool<<<dim3(8, 4, 32), 256, smem2>>>(x);
    k_flat<<<(Bb * Ff) / 256, 256>>>();
    k3_proj<<<dim3(32, 8), 256, smem1>>>(W);
    k_out<<<(Bb * Pp) / 256, 256>>>(bias, out);
}